// round 12
// baseline (speedup 1.0000x reference)
#include <cuda_runtime.h>
#include <cuda_fp16.h>
#include <stdint.h>

// ============================================================================
// SparseGradLinear, single fused persistent-dataflow kernel (fp16 HMMA):
//   phase0: W2part[z] = VT[:,z] @ weight[z,:]   (fp32 SIMT, 576 CTAs)
//   reduce: W2 = fp16(sum W2part)               (18 CTAs, waits p0done)
//   phase1: h  = threshold(fp16(x) @ fp16(U)^T) (1536 CTAs)
//   phase2: out = h @ W2^T + bias               (1536 CTAs, waits w2done+ready)
// All dependencies point to lower block ids -> deadlock-free; phase0/reduce
// hide entirely under phase1.
// ============================================================================

#define DIM    768
#define MROWS  32768
#define MBLKS  (MROWS / 128)   // 256
#define NBLKS  (DIM / 128)     // 6
#define NT1    (MBLKS * NBLKS) // 1536
#define NW2P   576             // phase-0 CTAs (12x12 tiles x 4 k-splits)
#define NRED   18              // reduce CTAs
#define BASE1  (NW2P + NRED)   // 594
#define BASE2  (BASE1 + NT1)   // 2130
#define GRIDSZ (BASE2 + NT1)   // 3666

__device__ __half    g_x0[(size_t)MROWS * DIM];
__device__ __half    g_h0[(size_t)MROWS * DIM];
__device__ __half    g_u0[DIM * DIM];
__device__ __half    g_w20[DIM * DIM];
__device__ float     g_w2part[4][DIM * DIM];
__device__ unsigned  g_ready[MBLKS];
__device__ unsigned  g_p0done;
__device__ unsigned  g_w2done;

// ---- helpers ----
__device__ __forceinline__ uint32_t smem_u32(const void* p) {
    uint32_t a;
    asm("{ .reg .u64 t; cvta.to.shared.u64 t, %1; cvt.u32.u64 %0, t; }"
        : "=r"(a) : "l"(p));
    return a;
}
__device__ __forceinline__ void cp16(uint32_t dst, const void* src) {
    asm volatile("cp.async.cg.shared.global [%0], [%1], 16;" :: "r"(dst), "l"(src));
}
__device__ __forceinline__ void ldsm4(uint32_t* r, uint32_t addr) {
    asm volatile("ldmatrix.sync.aligned.m8n8.x4.shared.b16 {%0,%1,%2,%3}, [%4];"
                 : "=r"(r[0]), "=r"(r[1]), "=r"(r[2]), "=r"(r[3]) : "r"(addr));
}
__device__ __forceinline__ void mma16816(float* d, const uint32_t* a,
                                         uint32_t b0, uint32_t b1) {
    asm volatile(
        "mma.sync.aligned.m16n8k16.row.col.f32.f16.f16.f32 "
        "{%0,%1,%2,%3}, {%4,%5,%6,%7}, {%8,%9}, {%0,%1,%2,%3};"
        : "+f"(d[0]), "+f"(d[1]), "+f"(d[2]), "+f"(d[3])
        : "r"(a[0]), "r"(a[1]), "r"(a[2]), "r"(a[3]), "r"(b0), "r"(b1));
}
__device__ __forceinline__ void spin_until(const unsigned* flag, unsigned target) {
    unsigned v;
    while (true) {
        asm volatile("ld.acquire.gpu.global.u32 %0, [%1];"
                     : "=r"(v) : "l"(flag) : "memory");
        if (v >= target) break;
        __nanosleep(200);
    }
}
__device__ __forceinline__ void release_add(unsigned* flag) {
    asm volatile("red.release.gpu.global.add.u32 [%0], 1;" :: "l"(flag) : "memory");
}

// ============================================================================
// Fused kernel — mainloop tile config
// ============================================================================
#define NCHUNK 24            // 768 / 32
#define BKB    64            // bytes of K per chunk-row (32 fp16)
#define ROWB   80            // padded row stride in bytes
#define MATB   (128 * ROWB)  // 10240 per operand tile
#define NSTAGE 4
#define STB    (2 * MATB)    // A + B per stage = 20480
#define GEMM_SMEM (NSTAGE * STB)   // 81920 -> 2 CTAs/SM

__global__ void __launch_bounds__(256, 2)
fused_all(const float* __restrict__ VT, const float* __restrict__ Wt,
          const __half* __restrict__ X, const __half* __restrict__ U,
          float* __restrict__ outF, const float* __restrict__ bias)
{
    extern __shared__ char smem[];
    const int bid = blockIdx.x;
    const int tid = threadIdx.x;

    // ======================= phase 0: W2 partials (fp32) =====================
    if (bid < NW2P) {
        float* As = (float*)smem;              // [16][68]
        float* Bs = (float*)(smem + 16 * 68 * 4);  // [16][64]

        const int kz = bid / 144;
        const int q  = bid % 144;
        const int bp = (q / 12) * 64;
        const int bc = (q % 12) * 64;
        const int kbeg = kz * (DIM / 4);
        const int kend = kbeg + (DIM / 4);
        float* C = &g_w2part[kz][0];

        const int tx = tid & 15;
        const int ty = tid >> 4;

        float acc[4][4] = {};

        for (int k0 = kbeg; k0 < kend; k0 += 16) {
            {
                const int r = tid >> 2;
                const int o4 = (tid & 3) * 4;
                float4 av = *(const float4*)(VT + (size_t)(bp + r) * DIM + k0 + o4);
                As[(o4 + 0) * 68 + r] = av.x; As[(o4 + 1) * 68 + r] = av.y;
                As[(o4 + 2) * 68 + r] = av.z; As[(o4 + 3) * 68 + r] = av.w;
            }
            {
                const int o  = tid >> 4;
                const int c4 = (tid & 15) * 4;
                *(float4*)&Bs[o * 64 + c4] =
                    *(const float4*)(Wt + (size_t)(k0 + o) * DIM + bc + c4);
            }
            __syncthreads();
#pragma unroll
            for (int o = 0; o < 16; o++) {
                float a[4], b[4];
#pragma unroll
                for (int i = 0; i < 4; i++) a[i] = As[o * 68 + ty * 4 + i];
#pragma unroll
                for (int j = 0; j < 4; j++) b[j] = Bs[o * 64 + tx * 4 + j];
#pragma unroll
                for (int i = 0; i < 4; i++)
#pragma unroll
                    for (int j = 0; j < 4; j++) acc[i][j] += a[i] * b[j];
            }
            __syncthreads();
        }

#pragma unroll
        for (int i = 0; i < 4; i++)
#pragma unroll
            for (int j = 0; j < 4; j++)
                C[(size_t)(bp + ty * 4 + i) * DIM + bc + tx * 4 + j] = acc[i][j];

        __threadfence();
        __syncthreads();
        if (tid == 0) release_add(&g_p0done);
        return;
    }

    // ======================= reduce: W2 -> fp16 ==============================
    if (bid < BASE1) {
        if (tid == 0) spin_until(&g_p0done, NW2P);
        __syncthreads();

        const int r = bid - NW2P;          // 0..17
        const int n = DIM * DIM;
        const float* P = &g_w2part[0][0];
        for (int i = r * 256 + tid; i < n; i += NRED * 256) {
            float v = P[i] + P[i + n] + P[i + 2 * n] + P[i + 3 * n];
            g_w20[i] = __float2half_rn(v);
        }
        __threadfence();
        __syncthreads();
        if (tid == 0) release_add(&g_w2done);
        return;
    }

    // ======================= phases 1 & 2: main GEMMs ========================
    const bool ph2 = (bid >= BASE2);
    const int idx = ph2 ? bid - BASE2 : bid - BASE1;
    const int mb = idx / NBLKS;
    const int nb = idx % NBLKS;
    const int bm = mb * 128;
    const int bn = nb * 128;

    const int lane = tid & 31;
    const int wid  = tid >> 5;
    const int wm   = wid >> 2;
    const int wn   = wid & 3;

    if (ph2) {
        if (tid == 0) {
            spin_until(&g_w2done, NRED);
            spin_until(&g_ready[mb], NBLKS);
        }
        __syncthreads();
    }

    const __half* A0 = ph2 ? g_h0  : X;
    const __half* B0 = ph2 ? g_w20 : U;

    const uint32_t sb = smem_u32(smem);
    const int lrow = tid >> 1;
    const int lqB  = (tid & 1) * 32;
    const char* gA0 = (const char*)(A0 + (size_t)(bm + lrow) * DIM) + lqB;
    const char* gB0 = (const char*)(B0 + (size_t)(bn + lrow) * DIM) + lqB;
    const uint32_t sdst = lrow * ROWB + lqB;

    auto load_chunk = [&](int c) {
        const uint32_t st = sb + (c % NSTAGE) * STB + sdst;
        const int kb = c * BKB;
        cp16(st,            gA0 + kb); cp16(st + 16,        gA0 + kb + 16);
        cp16(st + MATB,     gB0 + kb); cp16(st + MATB + 16, gB0 + kb + 16);
        asm volatile("cp.async.commit_group;" ::: "memory");
    };

    const int lr8 = ((lane >> 3) & 1) * 8 + (lane & 7);
    const int lcb = ((lane >> 4) & 1) * 16;
    const uint32_t aRow = wm * 64 + lr8;
    const uint32_t bRow = wn * 32 + lr8;

    float acc[4][4][4];
#pragma unroll
    for (int i = 0; i < 4; i++)
#pragma unroll
        for (int j = 0; j < 4; j++)
#pragma unroll
            for (int k = 0; k < 4; k++) acc[i][j][k] = 0.0f;

    load_chunk(0);
    load_chunk(1);
    load_chunk(2);

    for (int c = 0; c < NCHUNK; c++) {
        const int rem = NCHUNK - 1 - c;
        if (rem >= 2)      asm volatile("cp.async.wait_group 2;" ::: "memory");
        else if (rem == 1) asm volatile("cp.async.wait_group 1;" ::: "memory");
        else               asm volatile("cp.async.wait_group 0;" ::: "memory");
        __syncthreads();   // chunk c visible; compute(c-1) done -> stage reusable

        if (c + 3 < NCHUNK) load_chunk(c + 3);

        const uint32_t stg = sb + (c % NSTAGE) * STB;
#pragma unroll
        for (int ks = 0; ks < 2; ks++) {
            uint32_t af[4][4], bf[2][4];
#pragma unroll
            for (int mt = 0; mt < 4; mt++)
                ldsm4(af[mt], stg + (aRow + mt * 16) * ROWB + ks * 32 + lcb);
#pragma unroll
            for (int ng = 0; ng < 2; ng++)
                ldsm4(bf[ng], stg + MATB + (bRow + ng * 16) * ROWB + ks * 32 + lcb);

#pragma unroll
            for (int mt = 0; mt < 4; mt++)
#pragma unroll
                for (int nt = 0; nt < 4; nt++) {
                    const int ng = nt >> 1, p = nt & 1;
                    mma16816(acc[mt][nt], af[mt], bf[ng][p], bf[ng][p + 2]);
                }
        }
    }

    // ---- epilogue ----
    const int r0 = bm + wm * 64 + (lane >> 2);
    const int c0 = bn + wn * 32 + (lane & 3) * 2;
    if (!ph2) {
#pragma unroll
        for (int mt = 0; mt < 4; mt++)
#pragma unroll
            for (int nt = 0; nt < 4; nt++) {
                const int col = c0 + nt * 8;
#pragma unroll
                for (int half = 0; half < 2; half++) {
                    const int row = r0 + mt * 16 + half * 8;
                    float vx = acc[mt][nt][half * 2];
                    float vy = acc[mt][nt][half * 2 + 1];
                    vx = (fabsf(vx) > 1e-3f) ? vx : 0.0f;
                    vy = (fabsf(vy) > 1e-3f) ? vy : 0.0f;
                    __half2 hv;
                    hv.x = __float2half_rn(vx);
                    hv.y = __float2half_rn(vy);
                    *(__half2*)(g_h0 + (size_t)row * DIM + col) = hv;
                }
            }
        __threadfence();
        __syncthreads();
        if (tid == 0) release_add(&g_ready[mb]);
    } else {
#pragma unroll
        for (int mt = 0; mt < 4; mt++)
#pragma unroll
            for (int nt = 0; nt < 4; nt++) {
                const int col = c0 + nt * 8;
#pragma unroll
                for (int half = 0; half < 2; half++) {
                    const int row = r0 + mt * 16 + half * 8;
                    const float2 bb = *(const float2*)&bias[col];
                    float2 v = make_float2(acc[mt][nt][half * 2] + bb.x,
                                           acc[mt][nt][half * 2 + 1] + bb.y);
                    *(float2*)(outF + (size_t)row * DIM + col) = v;
                }
            }
    }
}

// ============================================================================
// Flag reset (graph-replay safe).
// ============================================================================
__global__ void zero_flags()
{
    if (threadIdx.x < MBLKS) g_ready[threadIdx.x] = 0;
    if (threadIdx.x == 0) { g_p0done = 0; g_w2done = 0; }
}

// ============================================================================
// Elementwise fp32 -> fp16 convert, float4-vectorized.
// ============================================================================
__global__ void convert_fp16(const float4* __restrict__ src,
                             __half* __restrict__ dst, int n4)
{
    int i = blockIdx.x * blockDim.x + threadIdx.x;
    if (i >= n4) return;
    float4 v = src[i];
    __half2 a, b;
    a.x = __float2half_rn(v.x); a.y = __float2half_rn(v.y);
    b.x = __float2half_rn(v.z); b.y = __float2half_rn(v.w);
    __half2* p = (__half2*)(dst + (size_t)i * 4);
    p[0] = a; p[1] = b;
}

// ============================================================================
// kernel_launch — inputs: x, weight, bias, U, VT; output fp32 [32768,768]
// ============================================================================
extern "C" void kernel_launch(void* const* d_in, const int* in_sizes, int n_in,
                              void* d_out, int out_size)
{
    const float* x      = (const float*)d_in[0];
    const float* weight = (const float*)d_in[1];
    const float* bias   = (const float*)d_in[2];
    const float* U      = (const float*)d_in[3];
    const float* VT     = (const float*)d_in[4];
    float* out          = (float*)d_out;

    __half *x0, *u0;
    cudaGetSymbolAddress((void**)&x0, g_x0);
    cudaGetSymbolAddress((void**)&u0, g_u0);

    cudaFuncSetAttribute(fused_all, cudaFuncAttributeMaxDynamicSharedMemorySize, GEMM_SMEM);

    const int M = in_sizes[0] / DIM;   // 32768

    zero_flags<<<1, 256>>>();
    {
        int n4 = M * DIM / 4;
        convert_fp16<<<(n4 + 255) / 256, 256>>>((const float4*)x, x0, n4);
    }
    {
        int n4 = DIM * DIM / 4;
        convert_fp16<<<(n4 + 255) / 256, 256>>>((const float4*)U, u0, n4);
    }

    // One fused kernel: W2 partials + reduce + GEMM1 + GEMM2 with
    // acquire/release dataflow sync (all edges point to lower bids).
    fused_all<<<GRIDSZ, 256, GEMM_SMEM>>>(VT, weight, x0, u0, out, bias);
}